// round 2
// baseline (speedup 1.0000x reference)
#include <cuda_runtime.h>
#include <math.h>

// Problem dims (fixed by the reference setup_inputs)
#define BB   2
#define NN   1024
#define HH   8
#define GG   8
#define HG   64            // H*G
#define NBATCH (BB*HG)     // 128 independent GEMM batches
#define NROWS  (BB*NN*HG)  // 131072 SH rows per side
#define DPAD 16            // 15 SH components padded to 16 for float4

// Scratch: Y_q / Y_k in [B, H, G, N, 16] layout (batch-major, row n, padded d)
__device__ float g_Yq[(size_t)NBATCH * NN * DPAD];
__device__ float g_Yk[(size_t)NBATCH * NN * DPAD];

// ---------------------------------------------------------------------------
// packed f32x2 helpers (Blackwell FFMA2 — only reachable via PTX)
// ---------------------------------------------------------------------------
__device__ __forceinline__ void fma2(unsigned long long& d,
                                     unsigned long long a,
                                     unsigned long long b)
{
    asm("fma.rn.f32x2 %0, %1, %2, %0;" : "+l"(d) : "l"(a), "l"(b));
}

__device__ __forceinline__ float2 unpack2(unsigned long long v)
{
    float2 r;
    asm("mov.b64 {%0, %1}, %2;" : "=f"(r.x), "=f"(r.y) : "l"(v));
    return r;
}

// ---------------------------------------------------------------------------
// Kernel 1: rotate -> normalize -> spherical harmonics for BOTH q and k.
// One thread per (side, b, n, h, g). 1/sqrt(15) folded into the q side.
// ---------------------------------------------------------------------------
__global__ void sh_expand_kernel(const float* __restrict__ q_in,
                                 const float* __restrict__ k_in,
                                 const float* __restrict__ rq_in,
                                 const float* __restrict__ rk_in)
{
    int gt = blockIdx.x * blockDim.x + threadIdx.x;
    if (gt >= 2 * NROWS) return;
    int which = gt >= NROWS;          // 0 -> q, 1 -> k
    int t = gt - which * NROWS;

    const float* v_in = which ? k_in : q_in;
    const float* r_in = which ? rk_in : rq_in;
    float scale = which ? 1.0f : 0.2581988897471611f;  // 1/sqrt(15)

    int hg = t & (HG - 1);       // h*G + g
    int bn = t >> 6;             // b*N + n
    int b  = bn >> 10;           // /N
    int n  = bn & (NN - 1);

    const float* q = v_in + (size_t)t * 3;
    const float* r = r_in + (size_t)bn * 9;
    float q0 = q[0], q1 = q[1], q2 = q[2];

    float vx = r[0]*q0 + r[1]*q1 + r[2]*q2;
    float vy = r[3]*q0 + r[4]*q1 + r[5]*q2;
    float vz = r[6]*q0 + r[7]*q1 + r[8]*q2;

    float nrm = sqrtf(vx*vx + vy*vy + vz*vz);
    float inv = 1.0f / fmaxf(nrm, 1e-12f);
    float x = vx*inv, y = vy*inv, z = vz*inv;
    float x2 = x*x, y2 = y*y, z2 = z*z;

    const float f1 = 0.4886025119029199f * scale;  // sqrt(3/(4pi))
    const float f2 = 0.6307831305050401f * scale;  // sqrt(5/(4pi))
    const float f3 = 0.7463526651802308f * scale;  // sqrt(7/(4pi))
    const float s3  = 1.7320508075688772f;
    const float s15 = 3.8729833462074170f;
    const float c1  = 0.6123724356957945f;         // sqrt(3/8)
    const float c3  = 0.7905694150420949f;         // sqrt(5/8)

    float Y0  = f1 * x;
    float Y1  = f1 * y;
    float Y2  = f1 * z;

    float Y3  = f2 * (s3 * x * z);
    float Y4  = f2 * (s3 * x * y);
    float Y5  = f2 * (y2 - 0.5f * (x2 + z2));
    float Y6  = f2 * (s3 * y * z);
    float Y7  = f2 * (0.5f * s3) * (z2 - x2);

    float Y8  = f3 * (c3 * x * (3.0f * z2 - x2));
    float Y9  = f3 * (s15 * x * y * z);
    float Y10 = f3 * (c1 * x * (4.0f * y2 - x2 - z2));
    float Y11 = f3 * (0.5f * y * (2.0f * y2 - 3.0f * x2 - 3.0f * z2));
    float Y12 = f3 * (c1 * z * (4.0f * y2 - x2 - z2));
    float Y13 = f3 * (0.5f * s15) * (y * (z2 - x2));
    float Y14 = f3 * (c3 * z * (z2 - 3.0f * x2));

    float* Y = which ? g_Yk : g_Yq;
    size_t obase = (((size_t)b * HG + hg) * NN + n) * DPAD;
    float4* o = (float4*)(Y + obase);
    o[0] = make_float4(Y0,  Y1,  Y2,  Y3);
    o[1] = make_float4(Y4,  Y5,  Y6,  Y7);
    o[2] = make_float4(Y8,  Y9,  Y10, Y11);
    o[3] = make_float4(Y12, Y13, Y14, 0.0f);
}

// ---------------------------------------------------------------------------
// Kernel 2: batched small-K GEMM with packed f32x2 FMA.
// scores[batch, n, m] = sum_d Yq[n,d] * Yk[m,d]
// 64x64 output tile per block, 256 threads, 4x4 micro-tile per thread.
// A tile stored DUPLICATED ({a,a} float2) so FFMA2 broadcast operand is a
// single 64-bit LDS; B tile is plain scalar [k][m] (pairs are contiguous).
// ---------------------------------------------------------------------------
__global__ void __launch_bounds__(256) score_gemm_kernel(float* __restrict__ out)
{
    __shared__ float2 AsD[15][64];   // [k][n] duplicated: AsD[k][n] = {a,a}
    __shared__ float  Bsf[15][64];   // [k][m]

    int batch = blockIdx.z;
    int n0 = blockIdx.y * 64;
    int m0 = blockIdx.x * 64;
    int tid = threadIdx.x;

    // Stage tiles: each thread loads one float4 of A and one of B (k-chunk c)
    int row = tid >> 2;          // 0..63
    int c   = tid & 3;           // 0..3  -> k = 4c..4c+3
    const float4* A4 = (const float4*)(g_Yq + (size_t)batch * NN * DPAD);
    const float4* B4 = (const float4*)(g_Yk + (size_t)batch * NN * DPAD);
    float4 va = A4[(size_t)(n0 + row) * 4 + c];
    float4 vb = B4[(size_t)(m0 + row) * 4 + c];
    int kb = c * 4;
    // pad column k=15 never read (loop stops at 15); only write k in [kb,kb+4)
    AsD[kb + 0][row] = make_float2(va.x, va.x);
    AsD[kb + 1][row] = make_float2(va.y, va.y);
    AsD[kb + 2][row] = make_float2(va.z, va.z);
    if (kb + 3 < 15) AsD[kb + 3][row] = make_float2(va.w, va.w);
    Bsf[kb + 0][row] = vb.x;
    Bsf[kb + 1][row] = vb.y;
    Bsf[kb + 2][row] = vb.z;
    if (kb + 3 < 15) Bsf[kb + 3][row] = vb.w;
    __syncthreads();

    int tx = tid & 15;           // m micro-tile (x4)
    int ty = tid >> 4;           // n micro-tile (x4)

    // acc[i][p]: row i (0..3), column pair p (0: m0+tx*4+{0,1}, 1: +{2,3})
    unsigned long long acc[4][2];
    #pragma unroll
    for (int i = 0; i < 4; i++) { acc[i][0] = 0ull; acc[i][1] = 0ull; }

    #pragma unroll
    for (int k = 0; k < 15; k++) {
        // a duplicated pairs: 4 x 64-bit, contiguous -> 2x LDS.128
        ulonglong2 a01 = *(const ulonglong2*)&AsD[k][ty * 4 + 0];
        ulonglong2 a23 = *(const ulonglong2*)&AsD[k][ty * 4 + 2];
        // b pairs: {b0,b1},{b2,b3} -> 1x LDS.128
        ulonglong2 b   = *(const ulonglong2*)&Bsf[k][tx * 4];

        fma2(acc[0][0], a01.x, b.x); fma2(acc[0][1], a01.x, b.y);
        fma2(acc[1][0], a01.y, b.x); fma2(acc[1][1], a01.y, b.y);
        fma2(acc[2][0], a23.x, b.x); fma2(acc[2][1], a23.x, b.y);
        fma2(acc[3][0], a23.y, b.x); fma2(acc[3][1], a23.y, b.y);
    }

    float* o = out + (size_t)batch * NN * NN + (size_t)n0 * NN + m0;
    #pragma unroll
    for (int i = 0; i < 4; i++) {
        float2 lo = unpack2(acc[i][0]);
        float2 hi = unpack2(acc[i][1]);
        float4 st = make_float4(lo.x, lo.y, hi.x, hi.y);
        __stcs((float4*)(o + (size_t)(ty * 4 + i) * NN) + tx, st);
    }
}

// ---------------------------------------------------------------------------
extern "C" void kernel_launch(void* const* d_in, const int* in_sizes, int n_in,
                              void* d_out, int out_size)
{
    const float* q  = (const float*)d_in[0];
    const float* k  = (const float*)d_in[1];
    const float* rq = (const float*)d_in[2];
    const float* rk = (const float*)d_in[3];
    float* out = (float*)d_out;

    int blocks = (2 * NROWS + 255) / 256;
    sh_expand_kernel<<<blocks, 256>>>(q, k, rq, rk);

    dim3 grid(NN / 64, NN / 64, NBATCH);  // 16 x 16 x 128
    score_gemm_kernel<<<grid, 256>>>(out);
}

// round 3
// speedup vs baseline: 1.2699x; 1.2699x over previous
#include <cuda_runtime.h>
#include <math.h>

// Problem dims (fixed by the reference setup_inputs)
#define BB   2
#define NN   1024
#define HG   64            // H*G
#define NBATCH (BB*HG)     // 128 independent GEMM batches
#define NROWS  (BB*NN*HG)  // 131072 SH rows per side
#define DPAD 16            // 15 SH components padded to 16 for float4

// Scratch: Y_q / Y_k in [B, H, G, N, 16] layout (batch-major, row n, padded d)
__device__ float g_Yq[(size_t)NBATCH * NN * DPAD];
__device__ float g_Yk[(size_t)NBATCH * NN * DPAD];

// ---------------------------------------------------------------------------
// packed f32x2 helpers (Blackwell FFMA2 — only reachable via PTX)
// ---------------------------------------------------------------------------
__device__ __forceinline__ void fma2(unsigned long long& d,
                                     unsigned long long a,
                                     unsigned long long b)
{
    asm("fma.rn.f32x2 %0, %1, %2, %0;" : "+l"(d) : "l"(a), "l"(b));
}

__device__ __forceinline__ float2 unpack2(unsigned long long v)
{
    float2 r;
    asm("mov.b64 {%0, %1}, %2;" : "=f"(r.x), "=f"(r.y) : "l"(v));
    return r;
}

// ---------------------------------------------------------------------------
// Kernel 1: rotate -> normalize -> spherical harmonics for BOTH q and k.
// One thread per (side, b, n, h, g). 1/sqrt(15) folded into the q side.
// ---------------------------------------------------------------------------
__global__ void sh_expand_kernel(const float* __restrict__ q_in,
                                 const float* __restrict__ k_in,
                                 const float* __restrict__ rq_in,
                                 const float* __restrict__ rk_in)
{
    int gt = blockIdx.x * blockDim.x + threadIdx.x;
    if (gt >= 2 * NROWS) return;
    int which = gt >= NROWS;          // 0 -> q, 1 -> k
    int t = gt - which * NROWS;

    const float* v_in = which ? k_in : q_in;
    const float* r_in = which ? rk_in : rq_in;
    float scale = which ? 1.0f : 0.2581988897471611f;  // 1/sqrt(15)

    int hg = t & (HG - 1);       // h*G + g
    int bn = t >> 6;             // b*N + n
    int b  = bn >> 10;           // /N
    int n  = bn & (NN - 1);

    const float* q = v_in + (size_t)t * 3;
    const float* r = r_in + (size_t)bn * 9;
    float q0 = q[0], q1 = q[1], q2 = q[2];

    float vx = r[0]*q0 + r[1]*q1 + r[2]*q2;
    float vy = r[3]*q0 + r[4]*q1 + r[5]*q2;
    float vz = r[6]*q0 + r[7]*q1 + r[8]*q2;

    float nrm = sqrtf(vx*vx + vy*vy + vz*vz);
    float inv = 1.0f / fmaxf(nrm, 1e-12f);
    float x = vx*inv, y = vy*inv, z = vz*inv;
    float x2 = x*x, y2 = y*y, z2 = z*z;

    const float f1 = 0.4886025119029199f * scale;  // sqrt(3/(4pi))
    const float f2 = 0.6307831305050401f * scale;  // sqrt(5/(4pi))
    const float f3 = 0.7463526651802308f * scale;  // sqrt(7/(4pi))
    const float s3  = 1.7320508075688772f;
    const float s15 = 3.8729833462074170f;
    const float c1  = 0.6123724356957945f;         // sqrt(3/8)
    const float c3  = 0.7905694150420949f;         // sqrt(5/8)

    float Y0  = f1 * x;
    float Y1  = f1 * y;
    float Y2  = f1 * z;

    float Y3  = f2 * (s3 * x * z);
    float Y4  = f2 * (s3 * x * y);
    float Y5  = f2 * (y2 - 0.5f * (x2 + z2));
    float Y6  = f2 * (s3 * y * z);
    float Y7  = f2 * (0.5f * s3) * (z2 - x2);

    float Y8  = f3 * (c3 * x * (3.0f * z2 - x2));
    float Y9  = f3 * (s15 * x * y * z);
    float Y10 = f3 * (c1 * x * (4.0f * y2 - x2 - z2));
    float Y11 = f3 * (0.5f * y * (2.0f * y2 - 3.0f * x2 - 3.0f * z2));
    float Y12 = f3 * (c1 * z * (4.0f * y2 - x2 - z2));
    float Y13 = f3 * (0.5f * s15) * (y * (z2 - x2));
    float Y14 = f3 * (c3 * z * (z2 - 3.0f * x2));

    float* Y = which ? g_Yk : g_Yq;
    size_t obase = (((size_t)b * HG + hg) * NN + n) * DPAD;
    float4* o = (float4*)(Y + obase);
    o[0] = make_float4(Y0,  Y1,  Y2,  Y3);
    o[1] = make_float4(Y4,  Y5,  Y6,  Y7);
    o[2] = make_float4(Y8,  Y9,  Y10, Y11);
    o[3] = make_float4(Y12, Y13, Y14, 0.0f);
}

// ---------------------------------------------------------------------------
// Kernel 2: batched small-K GEMM with packed f32x2 FMA.
// scores[batch, n, m] = sum_d Yq[n,d] * Yk[m,d]
// 128x128 output tile per block, 256 threads, 8x8 micro-tile per thread,
// split as 4+4 rows/cols (chunks at +0 and +64) so lane accesses are
// 16B-strided (conflict-free LDS, coalesced STG).
// A is duplicated {a,a} in smem (warp-broadcast, so LDS-cheap) to feed FFMA2
// without register packing; B pairs {b0,b1},{b2,b3} come straight from LDS.128.
// ---------------------------------------------------------------------------
__global__ void __launch_bounds__(256, 2) score_gemm_kernel(float* __restrict__ out)
{
    __shared__ __align__(16) float2 AsD[15][128];  // [k][n] duplicated pairs
    __shared__ __align__(16) float  Bs[15][128];   // [k][m]

    int batch = blockIdx.z;
    int n0 = blockIdx.y * 128;
    int m0 = blockIdx.x * 128;
    int tid = threadIdx.x;

    // ---- stage tiles (each thread: 2 float4 per side, coalesced) ----
    const float4* A4 = (const float4*)(g_Yq + (size_t)batch * NN * DPAD);
    const float4* B4 = (const float4*)(g_Yk + (size_t)batch * NN * DPAD);
    #pragma unroll
    for (int i = 0; i < 2; i++) {
        int idx = tid + i * 256;        // 0..511
        int row = idx >> 2;             // 0..127
        int c   = idx & 3;              // k-chunk
        float4 va = A4[(size_t)(n0 + row) * 4 + c];
        float4 vb = B4[(size_t)(m0 + row) * 4 + c];
        int kb = c * 4;
        AsD[kb + 0][row] = make_float2(va.x, va.x);
        AsD[kb + 1][row] = make_float2(va.y, va.y);
        AsD[kb + 2][row] = make_float2(va.z, va.z);
        if (kb + 3 < 15) AsD[kb + 3][row] = make_float2(va.w, va.w);
        Bs[kb + 0][row] = vb.x;
        Bs[kb + 1][row] = vb.y;
        Bs[kb + 2][row] = vb.z;
        if (kb + 3 < 15) Bs[kb + 3][row] = vb.w;
    }
    __syncthreads();

    int tx = tid & 15;           // m micro-tile
    int ty = tid >> 4;           // n micro-tile
    int na = ty * 4;             // rows na..na+3 and 64+na..64+na+3
    int ma = tx * 4;             // cols ma..ma+3 and 64+ma..64+ma+3

    // acc[r][p]: r = row (0..3 -> na+r, 4..7 -> 64+na+r-4)
    //            p = col pair (0,1 -> ma+{0,1},{2,3}; 2,3 -> 64+ma+{0,1},{2,3})
    unsigned long long acc[8][4];
    #pragma unroll
    for (int r = 0; r < 8; r++)
        #pragma unroll
        for (int p = 0; p < 4; p++) acc[r][p] = 0ull;

    #pragma unroll
    for (int k = 0; k < 15; k++) {
        // a: duplicated pairs, 4x LDS.128 (broadcast within warp)
        ulonglong2 aA0 = *(const ulonglong2*)&AsD[k][na + 0];      // rows na+0,1
        ulonglong2 aA1 = *(const ulonglong2*)&AsD[k][na + 2];      // rows na+2,3
        ulonglong2 aB0 = *(const ulonglong2*)&AsD[k][64 + na + 0];
        ulonglong2 aB1 = *(const ulonglong2*)&AsD[k][64 + na + 2];
        // b: natural pairs, 2x LDS.128 (16B lane stride, conflict-free)
        ulonglong2 bA = *(const ulonglong2*)&Bs[k][ma];        // {b0,b1},{b2,b3}
        ulonglong2 bB = *(const ulonglong2*)&Bs[k][64 + ma];

        fma2(acc[0][0], aA0.x, bA.x); fma2(acc[0][1], aA0.x, bA.y);
        fma2(acc[0][2], aA0.x, bB.x); fma2(acc[0][3], aA0.x, bB.y);
        fma2(acc[1][0], aA0.y, bA.x); fma2(acc[1][1], aA0.y, bA.y);
        fma2(acc[1][2], aA0.y, bB.x); fma2(acc[1][3], aA0.y, bB.y);
        fma2(acc[2][0], aA1.x, bA.x); fma2(acc[2][1], aA1.x, bA.y);
        fma2(acc[2][2], aA1.x, bB.x); fma2(acc[2][3], aA1.x, bB.y);
        fma2(acc[3][0], aA1.y, bA.x); fma2(acc[3][1], aA1.y, bA.y);
        fma2(acc[3][2], aA1.y, bB.x); fma2(acc[3][3], aA1.y, bB.y);
        fma2(acc[4][0], aB0.x, bA.x); fma2(acc[4][1], aB0.x, bA.y);
        fma2(acc[4][2], aB0.x, bB.x); fma2(acc[4][3], aB0.x, bB.y);
        fma2(acc[5][0], aB0.y, bA.x); fma2(acc[5][1], aB0.y, bA.y);
        fma2(acc[5][2], aB0.y, bB.x); fma2(acc[5][3], aB0.y, bB.y);
        fma2(acc[6][0], aB1.x, bA.x); fma2(acc[6][1], aB1.x, bA.y);
        fma2(acc[6][2], aB1.x, bB.x); fma2(acc[6][3], aB1.x, bB.y);
        fma2(acc[7][0], aB1.y, bA.x); fma2(acc[7][1], aB1.y, bA.y);
        fma2(acc[7][2], aB1.y, bB.x); fma2(acc[7][3], aB1.y, bB.y);
    }

    // ---- store: two coalesced float4 per row, 8 rows ----
    float* o = out + (size_t)batch * NN * NN + (size_t)n0 * NN + m0;
    #pragma unroll
    for (int r = 0; r < 8; r++) {
        int n = (r < 4) ? (na + r) : (64 + na + r - 4);
        float2 l0 = unpack2(acc[r][0]);
        float2 l1 = unpack2(acc[r][1]);
        float2 l2 = unpack2(acc[r][2]);
        float2 l3 = unpack2(acc[r][3]);
        float* orow = o + (size_t)n * NN;
        __stcs((float4*)(orow + ma),      make_float4(l0.x, l0.y, l1.x, l1.y));
        __stcs((float4*)(orow + 64 + ma), make_float4(l2.x, l2.y, l3.x, l3.y));
    }
}

// ---------------------------------------------------------------------------
extern "C" void kernel_launch(void* const* d_in, const int* in_sizes, int n_in,
                              void* d_out, int out_size)
{
    const float* q  = (const float*)d_in[0];
    const float* k  = (const float*)d_in[1];
    const float* rq = (const float*)d_in[2];
    const float* rk = (const float*)d_in[3];
    float* out = (float*)d_out;

    int blocks = (2 * NROWS + 255) / 256;
    sh_expand_kernel<<<blocks, 256>>>(q, k, rq, rk);

    dim3 grid(NN / 128, NN / 128, NBATCH);  // 8 x 8 x 128
    score_gemm_kernel<<<grid, 256>>>(out);
}